// round 12
// baseline (speedup 1.0000x reference)
#include <cuda_runtime.h>
#include <cstdint>

// Sliding-window gated attention (W=32, D=64) via tf32 mma.sync (sm_100-compatible).
// Per block: (b, h, 64 queries), 4 warps, each warp 16 queries x 48-col band.
//   stage: cp.async K -> smem (raw fp32); V is NOT staged (read from L2 in GEMM2)
//   wait K -> gate factors (MUFU overlaps) -> GEMM1 (inline rna cvt)
//   apply gates, D->A frag via shuffles
//   GEMM2 with B-fragments as guarded LDG straight from gmem/L2
// smem = K tile + a row only (26.5KB) -> 5 CTAs/SM (reg-capped).

constexpr int B_ = 2, S_ = 2048, H_ = 8, D_ = 64, W_ = 32;
constexpr int HD = H_ * D_;
constexpr int TS   = 64;
constexpr int NT   = 128;
constexpr int ROWS = 96;           // 95 needed, 96 for even split
constexpr int STRIDE = 68;         // conflict-free: (gid*68+tig) mod 32 = 4*gid+tig
constexpr float SCALE = 0.125f;

constexpr int OFF_K = 0;
constexpr int SZ_K  = ROWS * STRIDE;            // 6528
constexpr int OFF_A = OFF_K + SZ_K;
constexpr int SMEM_FLOATS = OFF_A + ROWS;       // 6624 floats = 26496 B

__device__ __forceinline__ float f2tf32(float x) {
    uint32_t r; asm("cvt.rna.tf32.f32 %0, %1;" : "=r"(r) : "f"(x));
    return __uint_as_float(r);
}
__device__ __forceinline__ uint32_t bits(float x) { return __float_as_uint(x); }
__device__ __forceinline__ uint32_t tfb(float x) {          // rna tf32 bits
    uint32_t r; asm("cvt.rna.tf32.f32 %0, %1;" : "=r"(r) : "f"(x));
    return r;
}

__device__ __forceinline__ uint32_t smem_u32(const void* p) {
    uint32_t a;
    asm("{ .reg .u64 t; cvta.to.shared.u64 t, %1; cvt.u32.u64 %0, t; }" : "=r"(a) : "l"(p));
    return a;
}
__device__ __forceinline__ void cp16(uint32_t dst, const void* src, int srcsize) {
    asm volatile("cp.async.cg.shared.global [%0], [%1], 16, %2;"
                 :: "r"(dst), "l"(src), "r"(srcsize) : "memory");
}

__device__ __forceinline__ void mma_tf32(float* d,
                                         uint32_t a0, uint32_t a1, uint32_t a2, uint32_t a3,
                                         uint32_t b0, uint32_t b1) {
    asm volatile("mma.sync.aligned.m16n8k8.row.col.f32.tf32.tf32.f32 "
                 "{%0,%1,%2,%3}, {%4,%5,%6,%7}, {%8,%9}, {%0,%1,%2,%3};"
                 : "+f"(d[0]), "+f"(d[1]), "+f"(d[2]), "+f"(d[3])
                 : "r"(a0), "r"(a1), "r"(a2), "r"(a3), "r"(b0), "r"(b1));
}

__global__ __launch_bounds__(NT, 5)
void swa_mma9_kernel(const float* __restrict__ qg,
                     const float* __restrict__ kg,
                     const float* __restrict__ vg,
                     const float* __restrict__ ag,
                     const float* __restrict__ bg,
                     float* __restrict__ outg)
{
    extern __shared__ float sm[];
    float* ks   = sm + OFF_K;
    float* a_sm = sm + OFF_A;
    const uint32_t smb = smem_u32(sm);

    const int s0  = blockIdx.x * TS;
    const int h   = blockIdx.y;
    const int bb  = blockIdx.z;
    const int tid = threadIdx.x;
    const int lane = tid & 31;
    const int gid  = lane >> 2;
    const int tig  = lane & 3;
    const int qb   = (tid >> 5) * 16;
    const size_t headBase = (size_t)bb * S_ * HD + (size_t)h * D_;

    // ---- Issue K staging (raw fp32; zero-fill OOB rows) ----
#pragma unroll
    for (int i = 0; i < 12; i++) {
        const int idx = tid + i * NT;          // 0..1535
        const int r = idx >> 4, c4 = (idx & 15) << 2;
        const int j = s0 - (W_ - 1) + r;
        const bool ok = (j >= 0) && (j < S_);
        const int jc = ok ? j : 0;
        const size_t off = headBase + (size_t)jc * HD + c4;
        cp16(smb + (uint32_t)(OFF_K + r * STRIDE + c4) * 4u, kg + off, ok ? 16 : 0);
    }
    asm volatile("cp.async.commit_group;" ::: "memory");

    // ---- Q fragments from gmem (overlap cp.async) ----
    const float* qrow0 = qg + headBase + (size_t)(s0 + qb + gid) * HD;
    const float* qrow1 = qrow0 + (size_t)8 * HD;
    uint32_t qa[8][4];
#pragma unroll
    for (int kk = 0; kk < 8; kk++) {
        const int c = kk * 8 + tig;
        qa[kk][0] = tfb(qrow0[c]);
        qa[kk][1] = tfb(qrow1[c]);
        qa[kk][2] = tfb(qrow0[c + 4]);
        qa[kk][3] = tfb(qrow1[c + 4]);
    }
    const float bq0 = bg[((size_t)bb * S_ + (s0 + qb + gid)) * H_ + h];
    const float bq1 = bg[((size_t)bb * S_ + (s0 + qb + gid + 8)) * H_ + h];
    if (tid < ROWS) {
        const int j = s0 - (W_ - 1) + tid;
        a_sm[tid] = (j >= 0 && j < S_) ? ag[((size_t)bb * S_ + j) * H_ + h] : 0.f;
    }

    // ---- K ready; publish via barrier ----
    asm volatile("cp.async.wait_group 0;" ::: "memory");
    __syncthreads();

    // ---- Gate factors BEFORE GEMM1: gf = SCALE*sigmoid(a_l*b_q)*mask ----
    float gf[6][4];
#pragma unroll
    for (int nt = 0; nt < 6; nt++) {
        const int colbase = nt * 8 + 2 * tig;
        const float a0 = a_sm[qb + colbase];
        const float a1 = a_sm[qb + colbase + 1];
#pragma unroll
        for (int e = 0; e < 4; e++) {
            const int row = (e >= 2) ? gid + 8 : gid;
            const int col = colbase + (e & 1);
            const int l   = qb + col;
            const int j   = s0 - (W_ - 1) + l;
            const int d   = col - row;
            const bool ok = (d >= 0) && (d < W_) && (j >= 0);
            const float av = (e & 1) ? a1 : a0;
            const float bq = (e >= 2) ? bq1 : bq0;
            const float g = __fdividef(SCALE, 1.f + __expf(-av * bq));
            gf[nt][e] = ok ? g : 0.f;
        }
    }

    // ---- GEMM1: S[16,48] = Q @ K^T (inline cvt of raw K fragments) ----
    float acc[6][4] = {};
#pragma unroll
    for (int kk = 0; kk < 8; kk++) {
#pragma unroll
        for (int nt = 0; nt < 6; nt++) {
            const float* kp = ks + (qb + nt * 8 + gid) * STRIDE + kk * 8 + tig;
            mma_tf32(acc[nt], qa[kk][0], qa[kk][1], qa[kk][2], qa[kk][3],
                     tfb(kp[0]), tfb(kp[4]));
        }
    }

    // ---- Apply gates; D-frag -> A-frag via shuffles ----
    const int srcA = (lane & 28) | ((lane & 3) >> 1);
    const int srcB = srcA + 2;
    const bool odd = (lane & 1) != 0;
    uint32_t wa[6][4];
#pragma unroll
    for (int nt = 0; nt < 6; nt++) {
        float w[4];
#pragma unroll
        for (int e = 0; e < 4; e++)
            w[e] = f2tf32(acc[nt][e] * gf[nt][e]);
        const float s00 = __shfl_sync(0xffffffffu, w[0], srcA);
        const float s10 = __shfl_sync(0xffffffffu, w[1], srcA);
        const float s20 = __shfl_sync(0xffffffffu, w[2], srcA);
        const float s30 = __shfl_sync(0xffffffffu, w[3], srcA);
        const float s01 = __shfl_sync(0xffffffffu, w[0], srcB);
        const float s11 = __shfl_sync(0xffffffffu, w[1], srcB);
        const float s21 = __shfl_sync(0xffffffffu, w[2], srcB);
        const float s31 = __shfl_sync(0xffffffffu, w[3], srcB);
        wa[nt][0] = bits(odd ? s10 : s00);    // W[gid][tig]
        wa[nt][1] = bits(odd ? s30 : s20);    // W[gid+8][tig]
        wa[nt][2] = bits(odd ? s11 : s01);    // W[gid][tig+4]
        wa[nt][3] = bits(odd ? s31 : s21);    // W[gid+8][tig+4]
    }

    // ---- GEMM2: O[16,64] = W[16,48] @ V[48,64], B frags via guarded LDG ----
    float oacc[8][4] = {};
#pragma unroll
    for (int kk = 0; kk < 6; kk++) {
        const int j0 = s0 - (W_ - 1) + qb + kk * 8 + tig;   // V row for b0
        const int j1 = j0 + 4;                              // V row for b1
        const bool ok0 = (j0 >= 0) && (j0 < S_);
        const bool ok1 = (j1 >= 0) && (j1 < S_);
        const float* vr0 = vg + headBase + (size_t)(ok0 ? j0 : 0) * HD + gid;
        const float* vr1 = vg + headBase + (size_t)(ok1 ? j1 : 0) * HD + gid;
#pragma unroll
        for (int nt = 0; nt < 8; nt++) {
            const float b0 = ok0 ? vr0[nt * 8] : 0.f;
            const float b1 = ok1 ? vr1[nt * 8] : 0.f;
            mma_tf32(oacc[nt], wa[kk][0], wa[kk][1], wa[kk][2], wa[kk][3],
                     tfb(b0), tfb(b1));
        }
    }

    // ---- Store O ----
    float* d0 = outg + headBase + (size_t)(s0 + qb + gid) * HD + 2 * tig;
    float* d1 = d0 + (size_t)8 * HD;
#pragma unroll
    for (int nt = 0; nt < 8; nt++) {
        *(float2*)(d0 + nt * 8) = make_float2(oacc[nt][0], oacc[nt][1]);
        *(float2*)(d1 + nt * 8) = make_float2(oacc[nt][2], oacc[nt][3]);
    }
}

extern "C" void kernel_launch(void* const* d_in, const int* in_sizes, int n_in,
                              void* d_out, int out_size)
{
    const float* q = (const float*)d_in[0];
    const float* k = (const float*)d_in[1];
    const float* v = (const float*)d_in[2];
    const float* a = (const float*)d_in[3];
    const float* b = (const float*)d_in[4];
    float* out = (float*)d_out;

    const int smem = SMEM_FLOATS * (int)sizeof(float);   // 26496 B
    cudaFuncSetAttribute(swa_mma9_kernel,
                         cudaFuncAttributeMaxDynamicSharedMemorySize, smem);
    dim3 grid(S_ / TS, H_, B_);
    swa_mma9_kernel<<<grid, NT, smem>>>(q, k, v, a, b, out);
}

// round 13
// speedup vs baseline: 1.0156x; 1.0156x over previous
#include <cuda_runtime.h>
#include <cstdint>

// Sliding-window gated attention (W=32, D=64) via tf32 mma.sync (sm_100-compatible).
// Per block: (b, h, 32 queries), 4 warps, each warp 8 queries x 40-col band
// (m16n8k8 fragments with upper 8 rows zero).
//   stage: cp.async K (group A), V (group B) -> smem (raw fp32)
//   wait K -> gate factors -> GEMM1 (inline rna cvt)
//   apply gates, D->A frag via shuffles
//   wait V -> GEMM2

constexpr int B_ = 2, S_ = 2048, H_ = 8, D_ = 64, W_ = 32;
constexpr int HD = H_ * D_;
constexpr int TS   = 32;
constexpr int NT   = 128;
constexpr int ROWS = 64;           // 63 needed, 64 for even split
constexpr int STRIDE = 68;         // conflict-free: (gid*68+tig) mod 32 = 4*gid+tig
constexpr float SCALE = 0.125f;

constexpr int OFF_K = 0;
constexpr int SZ_K  = ROWS * STRIDE;            // 4352
constexpr int OFF_V = OFF_K + SZ_K;
constexpr int OFF_A = OFF_V + SZ_K;
constexpr int SMEM_FLOATS = OFF_A + ROWS;       // 8768 floats = 35072 B -> 5 CTAs/SM

__device__ __forceinline__ float f2tf32(float x) {
    uint32_t r; asm("cvt.rna.tf32.f32 %0, %1;" : "=r"(r) : "f"(x));
    return __uint_as_float(r);
}
__device__ __forceinline__ uint32_t bits(float x) { return __float_as_uint(x); }
__device__ __forceinline__ uint32_t tfb(float x) {          // rna tf32 bits
    uint32_t r; asm("cvt.rna.tf32.f32 %0, %1;" : "=r"(r) : "f"(x));
    return r;
}

__device__ __forceinline__ uint32_t smem_u32(const void* p) {
    uint32_t a;
    asm("{ .reg .u64 t; cvta.to.shared.u64 t, %1; cvt.u32.u64 %0, t; }" : "=r"(a) : "l"(p));
    return a;
}
__device__ __forceinline__ void cp16(uint32_t dst, const void* src, int srcsize) {
    asm volatile("cp.async.cg.shared.global [%0], [%1], 16, %2;"
                 :: "r"(dst), "l"(src), "r"(srcsize) : "memory");
}

__device__ __forceinline__ void mma_tf32(float* d,
                                         uint32_t a0, uint32_t a1, uint32_t a2, uint32_t a3,
                                         uint32_t b0, uint32_t b1) {
    asm volatile("mma.sync.aligned.m16n8k8.row.col.f32.tf32.tf32.f32 "
                 "{%0,%1,%2,%3}, {%4,%5,%6,%7}, {%8,%9}, {%0,%1,%2,%3};"
                 : "+f"(d[0]), "+f"(d[1]), "+f"(d[2]), "+f"(d[3])
                 : "r"(a0), "r"(a1), "r"(a2), "r"(a3), "r"(b0), "r"(b1));
}

__global__ __launch_bounds__(NT, 5)
void swa_mma10_kernel(const float* __restrict__ qg,
                      const float* __restrict__ kg,
                      const float* __restrict__ vg,
                      const float* __restrict__ ag,
                      const float* __restrict__ bg,
                      float* __restrict__ outg)
{
    extern __shared__ float sm[];
    float* ks   = sm + OFF_K;
    float* vs   = sm + OFF_V;
    float* a_sm = sm + OFF_A;
    const uint32_t smb = smem_u32(sm);

    const int s0  = blockIdx.x * TS;
    const int h   = blockIdx.y;
    const int bb  = blockIdx.z;
    const int tid = threadIdx.x;
    const int lane = tid & 31;
    const int gid  = lane >> 2;
    const int tig  = lane & 3;
    const int qb   = (tid >> 5) * 8;       // warp's first local query (8 per warp)
    const size_t headBase = (size_t)bb * S_ * HD + (size_t)h * D_;

    // ---- Issue K staging (group A), then V staging (group B), raw fp32 ----
#pragma unroll
    for (int i = 0; i < 8; i++) {
        const int idx = tid + i * NT;          // 0..1023
        const int r = idx >> 4, c4 = (idx & 15) << 2;
        const int j = s0 - (W_ - 1) + r;
        const bool ok = (j >= 0) && (j < S_);
        const int jc = ok ? j : 0;
        const size_t off = headBase + (size_t)jc * HD + c4;
        cp16(smb + (uint32_t)(OFF_K + r * STRIDE + c4) * 4u, kg + off, ok ? 16 : 0);
    }
    asm volatile("cp.async.commit_group;" ::: "memory");
#pragma unroll
    for (int i = 0; i < 8; i++) {
        const int idx = tid + i * NT;
        const int r = idx >> 4, c4 = (idx & 15) << 2;
        const int j = s0 - (W_ - 1) + r;
        const bool ok = (j >= 0) && (j < S_);
        const int jc = ok ? j : 0;
        const size_t off = headBase + (size_t)jc * HD + c4;
        cp16(smb + (uint32_t)(OFF_V + r * STRIDE + c4) * 4u, vg + off, ok ? 16 : 0);
    }
    asm volatile("cp.async.commit_group;" ::: "memory");

    // ---- Q fragments from gmem (rows 0..7 only; overlap cp.async) ----
    const float* qrow0 = qg + headBase + (size_t)(s0 + qb + gid) * HD;
    uint32_t qa[8][2];
#pragma unroll
    for (int kk = 0; kk < 8; kk++) {
        const int c = kk * 8 + tig;
        qa[kk][0] = tfb(qrow0[c]);
        qa[kk][1] = tfb(qrow0[c + 4]);
    }
    const float bq0 = bg[((size_t)bb * S_ + (s0 + qb + gid)) * H_ + h];
    if (tid < ROWS) {
        const int j = s0 - (W_ - 1) + tid;
        a_sm[tid] = (j >= 0 && j < S_) ? ag[((size_t)bb * S_ + j) * H_ + h] : 0.f;
    }

    // ---- K ready (V still in flight); publish via barrier ----
    asm volatile("cp.async.wait_group 1;" ::: "memory");
    __syncthreads();

    // ---- Gate factors BEFORE GEMM1: gf = SCALE*sigmoid(a_l*b_q)*mask ----
    float gf[5][2];
#pragma unroll
    for (int nt = 0; nt < 5; nt++) {
        const int colbase = nt * 8 + 2 * tig;
        const float a0 = a_sm[qb + colbase];
        const float a1 = a_sm[qb + colbase + 1];
#pragma unroll
        for (int e = 0; e < 2; e++) {
            const int col = colbase + e;
            const int l   = qb + col;
            const int j   = s0 - (W_ - 1) + l;
            const int d   = col - gid;
            const bool ok = (d >= 0) && (d < W_) && (j >= 0);
            const float av = e ? a1 : a0;
            const float g = __fdividef(SCALE, 1.f + __expf(-av * bq0));
            gf[nt][e] = ok ? g : 0.f;
        }
    }

    const uint32_t zr = 0u;   // zero operand for unused fragment rows 8..15

    // ---- GEMM1: S[8,40] = Q @ K^T (inline cvt of raw K fragments) ----
    float acc[5][4] = {};
#pragma unroll
    for (int kk = 0; kk < 8; kk++) {
#pragma unroll
        for (int nt = 0; nt < 5; nt++) {
            const float* kp = ks + (qb + nt * 8 + gid) * STRIDE + kk * 8 + tig;
            mma_tf32(acc[nt], qa[kk][0], zr, qa[kk][1], zr,
                     tfb(kp[0]), tfb(kp[4]));
        }
    }

    // ---- Apply gates; D-frag -> A-frag via shuffles (rows 0..7) ----
    const int srcA = (lane & 28) | ((lane & 3) >> 1);
    const int srcB = srcA + 2;
    const bool odd = (lane & 1) != 0;
    uint32_t wa[5][2];
#pragma unroll
    for (int nt = 0; nt < 5; nt++) {
        const float w0 = f2tf32(acc[nt][0] * gf[nt][0]);
        const float w1 = f2tf32(acc[nt][1] * gf[nt][1]);
        const float s00 = __shfl_sync(0xffffffffu, w0, srcA);
        const float s10 = __shfl_sync(0xffffffffu, w1, srcA);
        const float s01 = __shfl_sync(0xffffffffu, w0, srcB);
        const float s11 = __shfl_sync(0xffffffffu, w1, srcB);
        wa[nt][0] = bits(odd ? s10 : s00);    // W[gid][nt*8+tig]
        wa[nt][1] = bits(odd ? s11 : s01);    // W[gid][nt*8+tig+4]
    }

    // ---- V ready; publish; GEMM2: O[8,64] = W[8,40] @ V[40,64] ----
    asm volatile("cp.async.wait_group 0;" ::: "memory");
    __syncthreads();

    float oacc[8][4] = {};
#pragma unroll
    for (int kk = 0; kk < 5; kk++) {
#pragma unroll
        for (int nt = 0; nt < 8; nt++) {
            const float* vp0 = vs + (qb + kk * 8 + tig) * STRIDE + nt * 8 + gid;
            const float* vp1 = vp0 + 4 * STRIDE;
            mma_tf32(oacc[nt], wa[kk][0], zr, wa[kk][1], zr,
                     tfb(vp0[0]), tfb(vp1[0]));
        }
    }

    // ---- Store O (rows 0..7 of each fragment) ----
    float* d0 = outg + headBase + (size_t)(s0 + qb + gid) * HD + 2 * tig;
#pragma unroll
    for (int nt = 0; nt < 8; nt++) {
        *(float2*)(d0 + nt * 8) = make_float2(oacc[nt][0], oacc[nt][1]);
    }
}

extern "C" void kernel_launch(void* const* d_in, const int* in_sizes, int n_in,
                              void* d_out, int out_size)
{
    const float* q = (const float*)d_in[0];
    const float* k = (const float*)d_in[1];
    const float* v = (const float*)d_in[2];
    const float* a = (const float*)d_in[3];
    const float* b = (const float*)d_in[4];
    float* out = (float*)d_out;

    const int smem = SMEM_FLOATS * (int)sizeof(float);   // 35072 B
    cudaFuncSetAttribute(swa_mma10_kernel,
                         cudaFuncAttributeMaxDynamicSharedMemorySize, smem);
    dim3 grid(S_ / TS, H_, B_);
    swa_mma10_kernel<<<grid, NT, smem>>>(q, k, v, a, b, out);
}